// round 15
// baseline (speedup 1.0000x reference)
#include <cuda_runtime.h>
#include <cuda_fp16.h>
#include <cstdint>

#define N_USERS 100000
#define N_ITEMS 50000
#define N_ROWS  150000          // users then items, matching d_out layout
#define NNZ_C   1600000
#define DIM     64

#define ROWS_PER_BLK 64
#define NBT_U   1563            // ceil(100000/64) user tensor-gemm blocks
#define NBT_I   782             // ceil(50000/64)  item tensor-gemm blocks

#define CAP_U   96              // max user degree (Poisson(16): P(>=96) ~ 1e-40)
#define CAP_I   128             // max item degree (Poisson(32))

#define WP_WORDS (8 * 32 * 20)  // packed B-fragment buffer, stride-20 padded

// ---- device scratch (no-alloc rule) ----
__device__ __half   g_xw_user[(size_t)N_USERS * DIM];      // 12.8 MB
__device__ __half   g_xw_item[(size_t)N_ITEMS * DIM];      //  6.4 MB
__device__ int      g_cnt[N_ROWS];                         // degree cursors
__device__ int2     g_perm_u[(size_t)N_USERS * CAP_U];     // 76.8 MB (src_item, val)
__device__ int2     g_perm_i[(size_t)N_ITEMS * CAP_I];     // 51.2 MB (src_user, val)
__device__ uint32_t g_wp[2][WP_WORDS];                     // packed W (user, item)

__device__ __forceinline__ uint32_t f2tf32(float f) {
    uint32_t r;
    asm("cvt.rna.tf32.f32 %0, %1;" : "=r"(r) : "f"(f));
    return r;
}

// ---------------------------------------------------------------------------
// One-time W pack: lane-major B-fragment layout Wp[kk][lane][16], padded to
// 20 words/lane (lane*20 mod 32 cycles all banks -> conflict-free LDS.128).
// Block 0 packs user_w, block 1 packs item_w.
// ---------------------------------------------------------------------------
__global__ __launch_bounds__(128) void wpack_kernel(
    const float* __restrict__ user_w, const float* __restrict__ item_w)
{
    const float* W   = blockIdx.x ? item_w : user_w;
    uint32_t*    dst = g_wp[blockIdx.x];
    for (int idx = threadIdx.x; idx < 8 * 32; idx += 128) {
        const int kk  = idx >> 5;
        const int ln  = idx & 31;
        const int gid = ln >> 2;
        const int tig = ln & 3;
        uint32_t* d = dst + kk * 640 + ln * 20;
        #pragma unroll
        for (int j = 0; j < 8; j++) {
            d[j * 2 + 0] = f2tf32(W[(kk * 8 + tig)     * 64 + j * 8 + gid]);
            d[j * 2 + 1] = f2tf32(W[(kk * 8 + tig + 4) * 64 + j * 8 + gid]);
        }
    }
}

// ---------------------------------------------------------------------------
// Tensor-core GEMM (tf32 mma.sync m16n8k8): Y = X @ W, K = N = 64,
// fp32 accumulate, fp16 output. 64 rows per 128-thread block.
//  - W fragments come pre-packed from g_wp (coalesced uint4 loads).
//  - X staged in smem (stride 68, conflict-free) as RAW fp32 bits; the
//    tf32 MMA consumes the top mantissa bits (RZ truncation) -- no CVTs.
// ---------------------------------------------------------------------------
__global__ __launch_bounds__(128) void gemm_tc_kernel(
    const float* __restrict__ user_x, const float* __restrict__ item_x)
{
    __shared__ uint32_t Xs[ROWS_PER_BLK * 68];     // fp32 bits, stride 68
    __shared__ uint32_t Wp[WP_WORDS];              // packed B frags, stride 20

    const int  tid     = threadIdx.x;
    const int  b       = blockIdx.x;
    const bool is_item = (b >= NBT_U);
    const int  gb      = is_item ? (b - NBT_U) : b;
    const int  nrows   = is_item ? N_ITEMS : N_USERS;
    const float* X     = is_item ? item_x : user_x;
    __half*      Y     = is_item ? g_xw_item : g_xw_user;
    const int  row0    = gb * ROWS_PER_BLK;

    // ---- load packed W: 1280 uint4, coalesced ----
    {
        const uint4* src = (const uint4*)g_wp[is_item ? 1 : 0];
        uint4*       dst = (uint4*)Wp;
        #pragma unroll
        for (int i = 0; i < 10; i++) dst[tid + i * 128] = src[tid + i * 128];
    }

    // ---- stage X tile (64 x 64), coalesced float4, raw bits ----
    #pragma unroll
    for (int i = 0; i < 8; i++) {
        const int idx = tid + i * 128;             // float4 index in tile
        const int r   = idx >> 4;
        const int c4  = (idx & 15) * 4;
        float4 v = make_float4(0.f, 0.f, 0.f, 0.f);
        if (row0 + r < nrows)
            v = *(const float4*)(X + (size_t)(row0 + r) * DIM + c4);
        uint32_t* dst = Xs + r * 68 + c4;
        dst[0] = __float_as_uint(v.x); dst[1] = __float_as_uint(v.y);
        dst[2] = __float_as_uint(v.z); dst[3] = __float_as_uint(v.w);
    }
    __syncthreads();

    const int warp = tid >> 5;
    const int lane = tid & 31;
    const int gid  = lane >> 2;
    const int tig  = lane & 3;
    const int wrow = warp * 16;

    float acc[8][4] = {};

    #pragma unroll
    for (int kk = 0; kk < 8; kk++) {
        const int kc = kk * 8 + tig;
        const uint32_t a0 = Xs[(wrow + gid)     * 68 + kc];
        const uint32_t a1 = Xs[(wrow + gid + 8) * 68 + kc];
        const uint32_t a2 = Xs[(wrow + gid)     * 68 + kc + 4];
        const uint32_t a3 = Xs[(wrow + gid + 8) * 68 + kc + 4];

        const uint4* wp4 = (const uint4*)(Wp + kk * 640 + lane * 20);
        const uint4 b01 = wp4[0];
        const uint4 b23 = wp4[1];
        const uint4 b45 = wp4[2];
        const uint4 b67 = wp4[3];

        #define MMA8(J, BH0, BH1)                                            \
            asm volatile(                                                    \
                "mma.sync.aligned.m16n8k8.row.col.f32.tf32.tf32.f32 "        \
                "{%0,%1,%2,%3}, {%4,%5,%6,%7}, {%8,%9}, {%0,%1,%2,%3};"      \
                : "+f"(acc[J][0]), "+f"(acc[J][1]),                          \
                  "+f"(acc[J][2]), "+f"(acc[J][3])                           \
                : "r"(a0), "r"(a1), "r"(a2), "r"(a3), "r"(BH0), "r"(BH1))
        MMA8(0, b01.x, b01.y);
        MMA8(1, b01.z, b01.w);
        MMA8(2, b23.x, b23.y);
        MMA8(3, b23.z, b23.w);
        MMA8(4, b45.x, b45.y);
        MMA8(5, b45.z, b45.w);
        MMA8(6, b67.x, b67.y);
        MMA8(7, b67.z, b67.w);
        #undef MMA8
    }

    const int r0 = row0 + wrow + gid;
    const int r1 = r0 + 8;
    const bool v0 = r0 < nrows;
    const bool v1 = r1 < nrows;
    #pragma unroll
    for (int j = 0; j < 8; j++) {
        const int col = j * 8 + 2 * tig;
        if (v0)
            *(__half2*)(Y + (size_t)r0 * DIM + col) =
                __floats2half2_rn(acc[j][0], acc[j][1]);
        if (v1)
            *(__half2*)(Y + (size_t)r1 * DIM + col) =
                __floats2half2_rn(acc[j][2], acc[j][3]);
    }
}

// ---------------------------------------------------------------------------
// Bucket edges, BOTH directions in one pass. 1 edge/thread.
// ---------------------------------------------------------------------------
__global__ __launch_bounds__(256) void perm_both_kernel(
    const int* __restrict__ rows, const int* __restrict__ cols,
    const float* __restrict__ vals)
{
    int e = blockIdx.x * blockDim.x + threadIdx.x;
    if (e >= NNZ_C) return;
    int r = rows[e];
    int c = cols[e];
    int v = __float_as_int(vals[e]);
    int s0 = atomicAdd(&g_cnt[r], 1);
    g_perm_u[(size_t)r * CAP_U + s0] = make_int2(c, v);
    int s1 = atomicAdd(&g_cnt[N_USERS + c], 1);
    g_perm_i[(size_t)c * CAP_I + s1] = make_int2(r, v);
}

// ---------------------------------------------------------------------------
// SpMM gather: one warp per output row. 8-lane groups process TWO edges
// (k, k+4) per iteration into independent accumulator sets -> 2x row-load
// chains in flight against L2 latency. fp16 sources, fp32 accumulation,
// cross-group shfl_xor reduction, fused ReLU.
// ---------------------------------------------------------------------------
__global__ __launch_bounds__(256) void spmm_gather_kernel(float* __restrict__ out)
{
    const int wid  = (blockIdx.x * blockDim.x + threadIdx.x) >> 5;
    const int lane = threadIdx.x & 31;
    if (wid >= N_ROWS) return;

    const int g  = lane >> 3;
    const int l8 = lane & 7;

    const int n = g_cnt[wid];
    const int2* __restrict__ bkt;
    const __half* __restrict__ src;
    if (wid < N_USERS) {
        bkt = g_perm_u + (size_t)wid * CAP_U;
        src = g_xw_item;
    } else {
        bkt = g_perm_i + (size_t)(wid - N_USERS) * CAP_I;
        src = g_xw_user;
    }

    float a0 = 0.f, a1 = 0.f, a2 = 0.f, a3 = 0.f;
    float a4 = 0.f, a5 = 0.f, a6 = 0.f, a7 = 0.f;
    float b0 = 0.f, b1 = 0.f, b2 = 0.f, b3 = 0.f;
    float b4 = 0.f, b5 = 0.f, b6 = 0.f, b7 = 0.f;

    for (int k = g; k < n; k += 8) {
        int2 pA = __ldg(bkt + k);
        const bool hasB = (k + 4) < n;
        int2 pB = hasB ? __ldg(bkt + k + 4) : make_int2(0, 0);  // dummy row, v=0

        const float vA = __int_as_float(pA.y);
        const float vB = __int_as_float(pB.y);

        uint4 hA = __ldg((const uint4*)(src + (size_t)pA.x * DIM) + l8);
        uint4 hB = __ldg((const uint4*)(src + (size_t)pB.x * DIM) + l8);

        float2 fA0 = __half22float2(*(__half2*)&hA.x);
        float2 fA1 = __half22float2(*(__half2*)&hA.y);
        float2 fA2 = __half22float2(*(__half2*)&hA.z);
        float2 fA3 = __half22float2(*(__half2*)&hA.w);
        a0 += vA * fA0.x; a1 += vA * fA0.y;
        a2 += vA * fA1.x; a3 += vA * fA1.y;
        a4 += vA * fA2.x; a5 += vA * fA2.y;
        a6 += vA * fA3.x; a7 += vA * fA3.y;

        float2 fB0 = __half22float2(*(__half2*)&hB.x);
        float2 fB1 = __half22float2(*(__half2*)&hB.y);
        float2 fB2 = __half22float2(*(__half2*)&hB.z);
        float2 fB3 = __half22float2(*(__half2*)&hB.w);
        b0 += vB * fB0.x; b1 += vB * fB0.y;
        b2 += vB * fB1.x; b3 += vB * fB1.y;
        b4 += vB * fB2.x; b5 += vB * fB2.y;
        b6 += vB * fB3.x; b7 += vB * fB3.y;
    }

    a0 += b0; a1 += b1; a2 += b2; a3 += b3;
    a4 += b4; a5 += b5; a6 += b6; a7 += b7;

    // sum across the 4 edge-groups (lanes l8, l8+8, l8+16, l8+24 share cols)
    a0 += __shfl_xor_sync(0xffffffffu, a0, 8);  a0 += __shfl_xor_sync(0xffffffffu, a0, 16);
    a1 += __shfl_xor_sync(0xffffffffu, a1, 8);  a1 += __shfl_xor_sync(0xffffffffu, a1, 16);
    a2 += __shfl_xor_sync(0xffffffffu, a2, 8);  a2 += __shfl_xor_sync(0xffffffffu, a2, 16);
    a3 += __shfl_xor_sync(0xffffffffu, a3, 8);  a3 += __shfl_xor_sync(0xffffffffu, a3, 16);
    a4 += __shfl_xor_sync(0xffffffffu, a4, 8);  a4 += __shfl_xor_sync(0xffffffffu, a4, 16);
    a5 += __shfl_xor_sync(0xffffffffu, a5, 8);  a5 += __shfl_xor_sync(0xffffffffu, a5, 16);
    a6 += __shfl_xor_sync(0xffffffffu, a6, 8);  a6 += __shfl_xor_sync(0xffffffffu, a6, 16);
    a7 += __shfl_xor_sync(0xffffffffu, a7, 8);  a7 += __shfl_xor_sync(0xffffffffu, a7, 16);

    if (g == 0) {
        float4* op = (float4*)(out + (size_t)wid * DIM) + l8 * 2;
        op[0] = make_float4(fmaxf(a0, 0.f), fmaxf(a1, 0.f),
                            fmaxf(a2, 0.f), fmaxf(a3, 0.f));
        op[1] = make_float4(fmaxf(a4, 0.f), fmaxf(a5, 0.f),
                            fmaxf(a6, 0.f), fmaxf(a7, 0.f));
    }
}

// ---------------------------------------------------------------------------
// Serial launch on stream 0 only.
// ---------------------------------------------------------------------------
extern "C" void kernel_launch(void* const* d_in, const int* in_sizes, int n_in,
                              void* d_out, int out_size)
{
    const float* user_x  = (const float*)d_in[0];
    const float* item_x  = (const float*)d_in[1];
    const float* user_w  = (const float*)d_in[2];
    const float* item_w  = (const float*)d_in[3];
    const int*   ui_rows = (const int*)d_in[4];
    const int*   ui_cols = (const int*)d_in[5];
    const float* ui_vals = (const float*)d_in[6];

    float* out = (float*)d_out;

    void* p_cnt = nullptr;
    cudaGetSymbolAddress(&p_cnt, g_cnt);

    // zero degree cursors
    cudaMemsetAsync(p_cnt, 0, N_ROWS * sizeof(int), 0);

    // pack W fragments once (2 tiny blocks)
    wpack_kernel<<<2, 128>>>(user_w, item_w);

    // both dense GEMMs on tensor cores (tf32, fp16 outputs)
    gemm_tc_kernel<<<NBT_U + NBT_I, 128>>>(user_x, item_x);

    // bucket edges, both directions, one pass over the edge list
    perm_both_kernel<<<(NNZ_C + 255) / 256, 256>>>(ui_rows, ui_cols, ui_vals);

    // gather SpMM with fused ReLU (writes every output row)
    spmm_gather_kernel<<<(N_ROWS * 32 + 255) / 256, 256>>>(out);
}

// round 16
// speedup vs baseline: 1.2239x; 1.2239x over previous
#include <cuda_runtime.h>
#include <cuda_fp16.h>
#include <cstdint>

#define N_USERS 100000
#define N_ITEMS 50000
#define N_ROWS  150000          // users then items, matching d_out layout
#define NNZ_C   1600000
#define DIM     64

#define ROWS_PER_BLK 64
#define NBT_U   1563            // ceil(100000/64) user tensor-gemm blocks
#define NBT_I   782             // ceil(50000/64)  item tensor-gemm blocks

#define CAP_U   96              // max user degree (Poisson(16): P(>=96) ~ 1e-40)
#define CAP_I   128             // max item degree (Poisson(32))

#define WP_WORDS (8 * 32 * 20)  // packed B-fragment buffer, stride-20 padded

// ---- device scratch (no-alloc rule) ----
__device__ __half   g_xw_user[(size_t)N_USERS * DIM];      // 12.8 MB
__device__ __half   g_xw_item[(size_t)N_ITEMS * DIM];      //  6.4 MB
__device__ int      g_cnt[N_ROWS];                         // degree cursors
__device__ int2     g_perm_u[(size_t)N_USERS * CAP_U];     // 76.8 MB (src_item, val)
__device__ int2     g_perm_i[(size_t)N_ITEMS * CAP_I];     // 51.2 MB (src_user, val)
__device__ uint32_t g_wp[2][WP_WORDS];                     // packed W (user, item)

__device__ __forceinline__ uint32_t f2tf32(float f) {
    uint32_t r;
    asm("cvt.rna.tf32.f32 %0, %1;" : "=r"(r) : "f"(f));
    return r;
}

// ---------------------------------------------------------------------------
// One-time W pack: lane-major B-fragment layout Wp[kk][lane][16], padded to
// 20 words/lane (lane*20 mod 32 cycles all banks -> conflict-free LDS.128).
// Block 0 packs user_w, block 1 packs item_w.
// ---------------------------------------------------------------------------
__global__ __launch_bounds__(128) void wpack_kernel(
    const float* __restrict__ user_w, const float* __restrict__ item_w)
{
    const float* W   = blockIdx.x ? item_w : user_w;
    uint32_t*    dst = g_wp[blockIdx.x];
    for (int idx = threadIdx.x; idx < 8 * 32; idx += 128) {
        const int kk  = idx >> 5;
        const int ln  = idx & 31;
        const int gid = ln >> 2;
        const int tig = ln & 3;
        uint32_t* d = dst + kk * 640 + ln * 20;
        #pragma unroll
        for (int j = 0; j < 8; j++) {
            d[j * 2 + 0] = f2tf32(W[(kk * 8 + tig)     * 64 + j * 8 + gid]);
            d[j * 2 + 1] = f2tf32(W[(kk * 8 + tig + 4) * 64 + j * 8 + gid]);
        }
    }
}

// ---------------------------------------------------------------------------
// Tensor-core GEMM (tf32 mma.sync m16n8k8): Y = X @ W, K = N = 64,
// fp32 accumulate, fp16 output. 64 rows per 128-thread block.
//  - W fragments pre-packed in g_wp (10 coalesced uint4 loads / thread).
//  - X staged in smem via coalesced float4, converted RNA->tf32, stride 68
//    (bank = (4*gid + tig) mod 32, all distinct -> conflict-free A-frags).
// ---------------------------------------------------------------------------
__global__ __launch_bounds__(128) void gemm_tc_kernel(
    const float* __restrict__ user_x, const float* __restrict__ item_x)
{
    __shared__ uint32_t Xs[ROWS_PER_BLK * 68];     // tf32 bits, stride 68
    __shared__ uint32_t Wp[WP_WORDS];              // packed B frags, stride 20

    const int  tid     = threadIdx.x;
    const int  b       = blockIdx.x;
    const bool is_item = (b >= NBT_U);
    const int  gb      = is_item ? (b - NBT_U) : b;
    const int  nrows   = is_item ? N_ITEMS : N_USERS;
    const float* X     = is_item ? item_x : user_x;
    __half*      Y     = is_item ? g_xw_item : g_xw_user;
    const int  row0    = gb * ROWS_PER_BLK;

    // ---- load packed W: 1280 uint4, coalesced ----
    {
        const uint4* src = (const uint4*)g_wp[is_item ? 1 : 0];
        uint4*       dst = (uint4*)Wp;
        #pragma unroll
        for (int i = 0; i < 10; i++) dst[tid + i * 128] = src[tid + i * 128];
    }

    // ---- stage X tile (64 x 64), coalesced float4, RNA tf32 bits ----
    #pragma unroll
    for (int i = 0; i < 8; i++) {
        const int idx = tid + i * 128;             // float4 index in tile
        const int r   = idx >> 4;
        const int c4  = (idx & 15) * 4;
        float4 v = make_float4(0.f, 0.f, 0.f, 0.f);
        if (row0 + r < nrows)
            v = *(const float4*)(X + (size_t)(row0 + r) * DIM + c4);
        uint32_t* dst = Xs + r * 68 + c4;
        dst[0] = f2tf32(v.x); dst[1] = f2tf32(v.y);
        dst[2] = f2tf32(v.z); dst[3] = f2tf32(v.w);
    }
    __syncthreads();

    const int warp = tid >> 5;
    const int lane = tid & 31;
    const int gid  = lane >> 2;
    const int tig  = lane & 3;
    const int wrow = warp * 16;

    float acc[8][4] = {};

    #pragma unroll
    for (int kk = 0; kk < 8; kk++) {
        const int kc = kk * 8 + tig;
        const uint32_t a0 = Xs[(wrow + gid)     * 68 + kc];
        const uint32_t a1 = Xs[(wrow + gid + 8) * 68 + kc];
        const uint32_t a2 = Xs[(wrow + gid)     * 68 + kc + 4];
        const uint32_t a3 = Xs[(wrow + gid + 8) * 68 + kc + 4];

        const uint4* wp4 = (const uint4*)(Wp + kk * 640 + lane * 20);
        const uint4 b01 = wp4[0];
        const uint4 b23 = wp4[1];
        const uint4 b45 = wp4[2];
        const uint4 b67 = wp4[3];

        #define MMA8(J, BH0, BH1)                                            \
            asm volatile(                                                    \
                "mma.sync.aligned.m16n8k8.row.col.f32.tf32.tf32.f32 "        \
                "{%0,%1,%2,%3}, {%4,%5,%6,%7}, {%8,%9}, {%0,%1,%2,%3};"      \
                : "+f"(acc[J][0]), "+f"(acc[J][1]),                          \
                  "+f"(acc[J][2]), "+f"(acc[J][3])                           \
                : "r"(a0), "r"(a1), "r"(a2), "r"(a3), "r"(BH0), "r"(BH1))
        MMA8(0, b01.x, b01.y);
        MMA8(1, b01.z, b01.w);
        MMA8(2, b23.x, b23.y);
        MMA8(3, b23.z, b23.w);
        MMA8(4, b45.x, b45.y);
        MMA8(5, b45.z, b45.w);
        MMA8(6, b67.x, b67.y);
        MMA8(7, b67.z, b67.w);
        #undef MMA8
    }

    const int r0 = row0 + wrow + gid;
    const int r1 = r0 + 8;
    const bool v0 = r0 < nrows;
    const bool v1 = r1 < nrows;
    #pragma unroll
    for (int j = 0; j < 8; j++) {
        const int col = j * 8 + 2 * tig;
        if (v0)
            *(__half2*)(Y + (size_t)r0 * DIM + col) =
                __floats2half2_rn(acc[j][0], acc[j][1]);
        if (v1)
            *(__half2*)(Y + (size_t)r1 * DIM + col) =
                __floats2half2_rn(acc[j][2], acc[j][3]);
    }
}

// ---------------------------------------------------------------------------
// Bucket edges, BOTH directions in one pass. 1 edge/thread.
// ---------------------------------------------------------------------------
__global__ __launch_bounds__(256) void perm_both_kernel(
    const int* __restrict__ rows, const int* __restrict__ cols,
    const float* __restrict__ vals)
{
    int e = blockIdx.x * blockDim.x + threadIdx.x;
    if (e >= NNZ_C) return;
    int r = rows[e];
    int c = cols[e];
    int v = __float_as_int(vals[e]);
    int s0 = atomicAdd(&g_cnt[r], 1);
    g_perm_u[(size_t)r * CAP_U + s0] = make_int2(c, v);
    int s1 = atomicAdd(&g_cnt[N_USERS + c], 1);
    g_perm_i[(size_t)c * CAP_I + s1] = make_int2(r, v);
}

// ---------------------------------------------------------------------------
// SpMM gather (R11-proven, 67.9us @ occ 80%, regs 32 -- DO NOT UNROLL: the
// 2-edge variant costs 11 regs -> occ 48% -> 102us, falsified 3x).
// One warp per output row; 8-lane groups each process one edge/iter; all 8
// lanes load the same perm entry (L1 broadcast). Each lane owns 8 columns
// via one LDG.128 of fp16. fp32 accumulation, cross-group shfl_xor
// reduction, fused ReLU.
// ---------------------------------------------------------------------------
__global__ __launch_bounds__(256) void spmm_gather_kernel(float* __restrict__ out)
{
    const int wid  = (blockIdx.x * blockDim.x + threadIdx.x) >> 5;
    const int lane = threadIdx.x & 31;
    if (wid >= N_ROWS) return;

    const int g  = lane >> 3;
    const int l8 = lane & 7;

    const int n = g_cnt[wid];
    const int2* __restrict__ bkt;
    const __half* __restrict__ src;
    if (wid < N_USERS) {
        bkt = g_perm_u + (size_t)wid * CAP_U;
        src = g_xw_item;
    } else {
        bkt = g_perm_i + (size_t)(wid - N_USERS) * CAP_I;
        src = g_xw_user;
    }

    float a0 = 0.f, a1 = 0.f, a2 = 0.f, a3 = 0.f;
    float a4 = 0.f, a5 = 0.f, a6 = 0.f, a7 = 0.f;

    for (int k = g; k < n; k += 4) {
        int2 p = __ldg(bkt + k);                       // broadcast within group
        const float v = __int_as_float(p.y);
        uint4 h = __ldg((const uint4*)(src + (size_t)p.x * DIM) + l8);
        float2 f0 = __half22float2(*(__half2*)&h.x);
        float2 f1 = __half22float2(*(__half2*)&h.y);
        float2 f2 = __half22float2(*(__half2*)&h.z);
        float2 f3 = __half22float2(*(__half2*)&h.w);
        a0 += v * f0.x; a1 += v * f0.y;
        a2 += v * f1.x; a3 += v * f1.y;
        a4 += v * f2.x; a5 += v * f2.y;
        a6 += v * f3.x; a7 += v * f3.y;
    }

    // sum across the 4 edge-groups (lanes l8, l8+8, l8+16, l8+24 share cols)
    a0 += __shfl_xor_sync(0xffffffffu, a0, 8);  a0 += __shfl_xor_sync(0xffffffffu, a0, 16);
    a1 += __shfl_xor_sync(0xffffffffu, a1, 8);  a1 += __shfl_xor_sync(0xffffffffu, a1, 16);
    a2 += __shfl_xor_sync(0xffffffffu, a2, 8);  a2 += __shfl_xor_sync(0xffffffffu, a2, 16);
    a3 += __shfl_xor_sync(0xffffffffu, a3, 8);  a3 += __shfl_xor_sync(0xffffffffu, a3, 16);
    a4 += __shfl_xor_sync(0xffffffffu, a4, 8);  a4 += __shfl_xor_sync(0xffffffffu, a4, 16);
    a5 += __shfl_xor_sync(0xffffffffu, a5, 8);  a5 += __shfl_xor_sync(0xffffffffu, a5, 16);
    a6 += __shfl_xor_sync(0xffffffffu, a6, 8);  a6 += __shfl_xor_sync(0xffffffffu, a6, 16);
    a7 += __shfl_xor_sync(0xffffffffu, a7, 8);  a7 += __shfl_xor_sync(0xffffffffu, a7, 16);

    if (g == 0) {
        float4* op = (float4*)(out + (size_t)wid * DIM) + l8 * 2;
        op[0] = make_float4(fmaxf(a0, 0.f), fmaxf(a1, 0.f),
                            fmaxf(a2, 0.f), fmaxf(a3, 0.f));
        op[1] = make_float4(fmaxf(a4, 0.f), fmaxf(a5, 0.f),
                            fmaxf(a6, 0.f), fmaxf(a7, 0.f));
    }
}

// ---------------------------------------------------------------------------
// Serial launch on stream 0 only.
// ---------------------------------------------------------------------------
extern "C" void kernel_launch(void* const* d_in, const int* in_sizes, int n_in,
                              void* d_out, int out_size)
{
    const float* user_x  = (const float*)d_in[0];
    const float* item_x  = (const float*)d_in[1];
    const float* user_w  = (const float*)d_in[2];
    const float* item_w  = (const float*)d_in[3];
    const int*   ui_rows = (const int*)d_in[4];
    const int*   ui_cols = (const int*)d_in[5];
    const float* ui_vals = (const float*)d_in[6];

    float* out = (float*)d_out;

    void* p_cnt = nullptr;
    cudaGetSymbolAddress(&p_cnt, g_cnt);

    // zero degree cursors
    cudaMemsetAsync(p_cnt, 0, N_ROWS * sizeof(int), 0);

    // pack W fragments once (2 tiny blocks)
    wpack_kernel<<<2, 128>>>(user_w, item_w);

    // both dense GEMMs on tensor cores (tf32, fp16 outputs)
    gemm_tc_kernel<<<NBT_U + NBT_I, 128>>>(user_x, item_x);

    // bucket edges, both directions, one pass over the edge list
    perm_both_kernel<<<(NNZ_C + 255) / 256, 256>>>(ui_rows, ui_cols, ui_vals);

    // gather SpMM with fused ReLU (writes every output row)
    spmm_gather_kernel<<<(N_ROWS * 32 + 255) / 256, 256>>>(out);
}